// round 3
// baseline (speedup 1.0000x reference)
#include <cuda_runtime.h>
#include <cuda_fp16.h>
#include <cstdint>

// ---------------------------------------------------------------------------
// Problem dims (fixed by the dataset)
// ---------------------------------------------------------------------------
#define GM 8192      // batch*seq = 4*2048
#define GN 4096      // out features
#define GK 4096      // in features

#define BM 128
#define BN 256
#define BK 64
#define KITERS (GK / BK)              // 64
#define STAGES 3
#define THREADS 256                   // 8 warps: 2 (M) x 4 (N), warp tile 64x64
#define TILES_M (GM / BM)             // 64
#define TILES_N (GN / BN)             // 16
#define NBLOCKS (TILES_M * TILES_N)   // 1024
#define RASTER_GROUP 8

#define A_BYTES (BM * BK * 2)         // 16384
#define B_BYTES (BN * BK * 2)         // 32768
#define STAGE_BYTES (A_BYTES + B_BYTES)             // 49152
#define SMEM_TOTAL (STAGES * STAGE_BYTES)           // 147456

// ---------------------------------------------------------------------------
// Device scratch (static — no runtime allocation allowed)
// ---------------------------------------------------------------------------
__device__ unsigned int g_absmax_bits[2];
__device__ __align__(16) __half g_Aq[(size_t)GM * GK];   // 64 MB
__device__ __align__(16) __half g_Bq[(size_t)GN * GK];   // 32 MB

// ---------------------------------------------------------------------------
// Helpers
// ---------------------------------------------------------------------------
__device__ __forceinline__ uint32_t smem_to_u32(const void* p) {
    uint32_t a;
    asm("{ .reg .u64 t; cvta.to.shared.u64 t, %1; cvt.u32.u64 %0, t; }"
        : "=r"(a) : "l"(p));
    return a;
}

__device__ __forceinline__ void cp_async16(uint32_t dst_smem, const void* src) {
    asm volatile("cp.async.cg.shared.global [%0], [%1], 16;\n"
                 :: "r"(dst_smem), "l"(src) : "memory");
}

__device__ __forceinline__ uint32_t swz(uint32_t x) {   // SW128: 128B rows
    return x ^ ((x >> 3) & 0x70);
}

__device__ __forceinline__ void ldsm_x4(uint32_t& r0, uint32_t& r1,
                                        uint32_t& r2, uint32_t& r3,
                                        uint32_t addr) {
    asm volatile("ldmatrix.sync.aligned.m8n8.x4.shared.b16 {%0,%1,%2,%3}, [%4];"
                 : "=r"(r0), "=r"(r1), "=r"(r2), "=r"(r3) : "r"(addr));
}

__device__ __forceinline__ void mma16816(float* c,
                                         uint32_t a0, uint32_t a1,
                                         uint32_t a2, uint32_t a3,
                                         uint32_t b0, uint32_t b1) {
    asm volatile(
        "mma.sync.aligned.m16n8k16.row.col.f32.f16.f16.f32 "
        "{%0,%1,%2,%3}, {%4,%5,%6,%7}, {%8,%9}, {%0,%1,%2,%3};"
        : "+f"(c[0]), "+f"(c[1]), "+f"(c[2]), "+f"(c[3])
        : "r"(a0), "r"(a1), "r"(a2), "r"(a3), "r"(b0), "r"(b1));
}

// ---------------------------------------------------------------------------
// Pass 1: abs-max reduction (deterministic: atomicMax on float-as-uint bits,
// all values non-negative so uint ordering == float ordering)
// ---------------------------------------------------------------------------
__global__ void init_kernel() {
    g_absmax_bits[0] = 0u;
    g_absmax_bits[1] = 0u;
}

__global__ void absmax_kernel(const float4* __restrict__ p, int nvec, int idx) {
    float m = 0.0f;
    for (int i = blockIdx.x * blockDim.x + threadIdx.x; i < nvec;
         i += gridDim.x * blockDim.x) {
        float4 v = p[i];
        m = fmaxf(m, fmaxf(fmaxf(fabsf(v.x), fabsf(v.y)),
                           fmaxf(fabsf(v.z), fabsf(v.w))));
    }
    #pragma unroll
    for (int o = 16; o > 0; o >>= 1)
        m = fmaxf(m, __shfl_xor_sync(0xffffffffu, m, o));
    __shared__ float sm[32];
    if ((threadIdx.x & 31) == 0) sm[threadIdx.x >> 5] = m;
    __syncthreads();
    if (threadIdx.x < 32) {
        m = (threadIdx.x < (blockDim.x >> 5)) ? sm[threadIdx.x] : 0.0f;
        #pragma unroll
        for (int o = 16; o > 0; o >>= 1)
            m = fmaxf(m, __shfl_xor_sync(0xffffffffu, m, o));
        if (threadIdx.x == 0)
            atomicMax(&g_absmax_bits[idx], __float_as_uint(m));
    }
}

// ---------------------------------------------------------------------------
// Pass 2: fake-quantize to integers in [-448,448], store fp16 (exact).
// round = rintf (half-to-even) matching jnp.round.
// ---------------------------------------------------------------------------
__global__ void quant_kernel(const float4* __restrict__ in, int nvec, int idx) {
    uint2* outv = (idx == 0) ? reinterpret_cast<uint2*>(g_Aq)
                             : reinterpret_cast<uint2*>(g_Bq);
    float amax = __uint_as_float(g_absmax_bits[idx]);
    float s = fmaxf(amax * (1.0f / 448.0f), 1e-12f);
    float inv = 1.0f / s;
    for (int i = blockIdx.x * blockDim.x + threadIdx.x; i < nvec;
         i += gridDim.x * blockDim.x) {
        float4 v = in[i];
        float q0 = rintf(fminf(fmaxf(v.x * inv, -448.0f), 448.0f));
        float q1 = rintf(fminf(fmaxf(v.y * inv, -448.0f), 448.0f));
        float q2 = rintf(fminf(fmaxf(v.z * inv, -448.0f), 448.0f));
        float q3 = rintf(fminf(fmaxf(v.w * inv, -448.0f), 448.0f));
        __half2 h0 = __floats2half2_rn(q0, q1);
        __half2 h1 = __floats2half2_rn(q2, q3);
        uint2 u;
        u.x = *reinterpret_cast<uint32_t*>(&h0);
        u.y = *reinterpret_cast<uint32_t*>(&h1);
        outv[i] = u;
    }
}

// ---------------------------------------------------------------------------
// Pass 3: HMMA GEMM  out[m,n] = (sum_k Aq[m,k]*Bq[n,k]) * scale + bias[n]
// BM=128 x BN=256 x BK=64, 3-stage cp.async pipeline, mma.sync m16n8k16.
// 256 threads = 8 warps in 2(M) x 4(N); warp tile 64 x 64.
// ---------------------------------------------------------------------------
__device__ __forceinline__ void load_stage(uint32_t smem_base, int s, int kt,
                                           int m0, int n0, int tid) {
    const uint32_t sa = smem_base + s * STAGE_BYTES;
    const uint32_t sb = sa + A_BYTES;
    const int kbase = kt * BK;
    // A: 128 rows x 8 chunks of 16B = 1024 chunks; 4 per thread
    #pragma unroll
    for (int i = 0; i < 4; i++) {
        int c = tid + i * THREADS;
        int row = c >> 3, col = c & 7;
        const __half* src = g_Aq + (size_t)(m0 + row) * GK + kbase + col * 8;
        cp_async16(sa + swz((uint32_t)(row * 128 + col * 16)), src);
    }
    // B: 256 rows x 8 chunks = 2048 chunks; 8 per thread
    #pragma unroll
    for (int i = 0; i < 8; i++) {
        int c = tid + i * THREADS;
        int row = c >> 3, col = c & 7;
        const __half* src = g_Bq + (size_t)(n0 + row) * GK + kbase + col * 8;
        cp_async16(sb + swz((uint32_t)(row * 128 + col * 16)), src);
    }
}

__global__ void __launch_bounds__(THREADS, 1)
gemm_kernel(const float* __restrict__ bias, float* __restrict__ out) {
    extern __shared__ char smem[];
    const uint32_t smem_base = smem_to_u32(smem);
    const int tid = threadIdx.x;
    const int wid = tid >> 5;
    const int lane = tid & 31;
    const int wm = wid & 1;        // 2 warps along M (64 rows each)
    const int wn = wid >> 1;       // 4 warps along N (64 cols each)

    // Supertile rasterization: bands of 8 m-tiles sweep all n-tiles (L2 reuse)
    int bid = blockIdx.x;
    int band = bid / (RASTER_GROUP * TILES_N);
    int rem  = bid % (RASTER_GROUP * TILES_N);
    int mt = band * RASTER_GROUP + (rem % RASTER_GROUP);
    int nt = rem / RASTER_GROUP;
    const int m0 = mt * BM;
    const int n0 = nt * BN;

    // acc[tm 4][tn 8][4] = 128 regs: warp tile 64x64
    float acc[4][8][4];
    #pragma unroll
    for (int i = 0; i < 4; i++)
        #pragma unroll
        for (int j = 0; j < 8; j++)
            #pragma unroll
            for (int v = 0; v < 4; v++)
                acc[i][j][v] = 0.0f;

    // prologue: fill STAGES-1 stages
    #pragma unroll
    for (int s = 0; s < STAGES - 1; s++) {
        load_stage(smem_base, s, s, m0, n0, tid);
        asm volatile("cp.async.commit_group;\n" ::: "memory");
    }

    // per-lane ldmatrix address components (byte offsets before swizzle)
    const uint32_t lrow = (uint32_t)(lane & 15) * 128u;   // row within 16-row tile
    const uint32_t lcol = (uint32_t)(lane >> 4) * 16u;    // k-half select

    #pragma unroll 1
    for (int kt = 0; kt < KITERS; kt++) {
        asm volatile("cp.async.wait_group %0;\n" :: "n"(STAGES - 2) : "memory");
        __syncthreads();

        if (kt + STAGES - 1 < KITERS)
            load_stage(smem_base, (kt + STAGES - 1) % STAGES, kt + STAGES - 1,
                       m0, n0, tid);
        asm volatile("cp.async.commit_group;\n" ::: "memory");

        const uint32_t sa = smem_base + (kt % STAGES) * STAGE_BYTES;
        const uint32_t sb = sa + A_BYTES;

        #pragma unroll
        for (int ks = 0; ks < 4; ks++) {
            const uint32_t koff = (uint32_t)ks * 32u + lcol;
            // A fragments: 4 x m16k16 (warp m64)
            uint32_t a[4][4];
            #pragma unroll
            for (int tm = 0; tm < 4; tm++) {
                uint32_t off = (uint32_t)(wm * 64 + tm * 16) * 128u + lrow + koff;
                ldsm_x4(a[tm][0], a[tm][1], a[tm][2], a[tm][3], sa + swz(off));
            }
            // B fragments: 4 x n16k16 (warp n64); 8 MMAs each
            #pragma unroll
            for (int tb = 0; tb < 4; tb++) {
                uint32_t b0, b1, b2, b3;
                uint32_t off = (uint32_t)(wn * 64 + tb * 16) * 128u + lrow + koff;
                ldsm_x4(b0, b1, b2, b3, sb + swz(off));
                #pragma unroll
                for (int tm = 0; tm < 4; tm++) {
                    mma16816(acc[tm][tb * 2 + 0], a[tm][0], a[tm][1], a[tm][2], a[tm][3], b0, b2);
                    mma16816(acc[tm][tb * 2 + 1], a[tm][0], a[tm][1], a[tm][2], a[tm][3], b1, b3);
                }
            }
        }
    }

    // ------------------------------------------------------------------
    // Epilogue: scale + bias
    // ------------------------------------------------------------------
    float s_in = fmaxf(__uint_as_float(g_absmax_bits[0]) * (1.0f / 448.0f), 1e-12f);
    float s_w  = fmaxf(__uint_as_float(g_absmax_bits[1]) * (1.0f / 448.0f), 1e-12f);
    float scale = s_in * s_w;

    const int col0 = n0 + wn * 64 + (lane & 3) * 2;
    float2 bv[8];
    #pragma unroll
    for (int tn = 0; tn < 8; tn++)
        bv[tn] = *reinterpret_cast<const float2*>(bias + col0 + tn * 8);

    #pragma unroll
    for (int tm = 0; tm < 4; tm++) {
        const int row0 = m0 + wm * 64 + tm * 16 + (lane >> 2);
        float* r0 = out + (size_t)row0 * GN;
        float* r1 = r0 + 8 * GN;
        #pragma unroll
        for (int tn = 0; tn < 8; tn++) {
            const int c = col0 + tn * 8;
            float2 v0, v1;
            v0.x = acc[tm][tn][0] * scale + bv[tn].x;
            v0.y = acc[tm][tn][1] * scale + bv[tn].y;
            v1.x = acc[tm][tn][2] * scale + bv[tn].x;
            v1.y = acc[tm][tn][3] * scale + bv[tn].y;
            *reinterpret_cast<float2*>(r0 + c) = v0;
            *reinterpret_cast<float2*>(r1 + c) = v1;
        }
    }
}

// ---------------------------------------------------------------------------
// Launch
// ---------------------------------------------------------------------------
extern "C" void kernel_launch(void* const* d_in, const int* in_sizes, int n_in,
                              void* d_out, int out_size) {
    const float* x    = (const float*)d_in[0];
    const float* w    = (const float*)d_in[1];
    const float* bias = (const float*)d_in[2];
    float* out        = (float*)d_out;

    init_kernel<<<1, 1>>>();
    absmax_kernel<<<2048, 256>>>((const float4*)x, (GM * GK) / 4, 0);
    absmax_kernel<<<1024, 256>>>((const float4*)w, (GN * GK) / 4, 1);
    quant_kernel<<<2048, 256>>>((const float4*)x, (GM * GK) / 4, 0);
    quant_kernel<<<1024, 256>>>((const float4*)w, (GN * GK) / 4, 1);

    cudaFuncSetAttribute(gemm_kernel,
                         cudaFuncAttributeMaxDynamicSharedMemorySize, SMEM_TOTAL);
    gemm_kernel<<<NBLOCKS, THREADS, SMEM_TOTAL>>>(bias, out);
}

// round 4
// speedup vs baseline: 1.0981x; 1.0981x over previous
#include <cuda_runtime.h>
#include <cuda_fp16.h>
#include <cstdint>

// ---------------------------------------------------------------------------
// Problem dims (fixed by the dataset)
// ---------------------------------------------------------------------------
#define GM 8192      // batch*seq = 4*2048
#define GN 4096      // out features
#define GK 4096      // in features

#define BM 128
#define BN 256
#define BK 64
#define KITERS (GK / BK)              // 64
#define STAGES 4
#define THREADS 512                   // 16 warps: 4 (M) x 4 (N), warp tile 32x64
#define TILES_M (GM / BM)             // 64
#define TILES_N (GN / BN)             // 16
#define NBLOCKS (TILES_M * TILES_N)   // 1024
#define RASTER_GROUP 8

#define A_BYTES (BM * BK * 2)         // 16384
#define B_BYTES (BN * BK * 2)         // 32768
#define STAGE_BYTES (A_BYTES + B_BYTES)             // 49152
#define SMEM_TOTAL (STAGES * STAGE_BYTES)           // 196608

// ---------------------------------------------------------------------------
// Device scratch (static — no runtime allocation allowed)
// ---------------------------------------------------------------------------
__device__ unsigned int g_absmax_bits[2];
__device__ __align__(16) __half g_Aq[(size_t)GM * GK];   // 64 MB
__device__ __align__(16) __half g_Bq[(size_t)GN * GK];   // 32 MB

// ---------------------------------------------------------------------------
// Helpers
// ---------------------------------------------------------------------------
__device__ __forceinline__ uint32_t smem_to_u32(const void* p) {
    uint32_t a;
    asm("{ .reg .u64 t; cvta.to.shared.u64 t, %1; cvt.u32.u64 %0, t; }"
        : "=r"(a) : "l"(p));
    return a;
}

__device__ __forceinline__ void cp_async16(uint32_t dst_smem, const void* src) {
    asm volatile("cp.async.cg.shared.global [%0], [%1], 16;\n"
                 :: "r"(dst_smem), "l"(src) : "memory");
}

__device__ __forceinline__ uint32_t swz(uint32_t x) {   // SW128: 128B rows
    return x ^ ((x >> 3) & 0x70);
}

__device__ __forceinline__ void ldsm_x4(uint32_t& r0, uint32_t& r1,
                                        uint32_t& r2, uint32_t& r3,
                                        uint32_t addr) {
    asm volatile("ldmatrix.sync.aligned.m8n8.x4.shared.b16 {%0,%1,%2,%3}, [%4];"
                 : "=r"(r0), "=r"(r1), "=r"(r2), "=r"(r3) : "r"(addr));
}

__device__ __forceinline__ void mma16816(float* c,
                                         uint32_t a0, uint32_t a1,
                                         uint32_t a2, uint32_t a3,
                                         uint32_t b0, uint32_t b1) {
    asm volatile(
        "mma.sync.aligned.m16n8k16.row.col.f32.f16.f16.f32 "
        "{%0,%1,%2,%3}, {%4,%5,%6,%7}, {%8,%9}, {%0,%1,%2,%3};"
        : "+f"(c[0]), "+f"(c[1]), "+f"(c[2]), "+f"(c[3])
        : "r"(a0), "r"(a1), "r"(a2), "r"(a3), "r"(b0), "r"(b1));
}

// ---------------------------------------------------------------------------
// Pass 1: abs-max reduction (deterministic: atomicMax on float-as-uint bits,
// all values non-negative so uint ordering == float ordering)
// ---------------------------------------------------------------------------
__global__ void init_kernel() {
    g_absmax_bits[0] = 0u;
    g_absmax_bits[1] = 0u;
}

__global__ void absmax_kernel(const float4* __restrict__ p, int nvec, int idx) {
    float m = 0.0f;
    for (int i = blockIdx.x * blockDim.x + threadIdx.x; i < nvec;
         i += gridDim.x * blockDim.x) {
        float4 v = p[i];
        m = fmaxf(m, fmaxf(fmaxf(fabsf(v.x), fabsf(v.y)),
                           fmaxf(fabsf(v.z), fabsf(v.w))));
    }
    #pragma unroll
    for (int o = 16; o > 0; o >>= 1)
        m = fmaxf(m, __shfl_xor_sync(0xffffffffu, m, o));
    __shared__ float sm[32];
    if ((threadIdx.x & 31) == 0) sm[threadIdx.x >> 5] = m;
    __syncthreads();
    if (threadIdx.x < 32) {
        m = (threadIdx.x < (blockDim.x >> 5)) ? sm[threadIdx.x] : 0.0f;
        #pragma unroll
        for (int o = 16; o > 0; o >>= 1)
            m = fmaxf(m, __shfl_xor_sync(0xffffffffu, m, o));
        if (threadIdx.x == 0)
            atomicMax(&g_absmax_bits[idx], __float_as_uint(m));
    }
}

// ---------------------------------------------------------------------------
// Pass 2: fake-quantize to integers in [-448,448], store fp16 (exact).
// round = rintf (half-to-even) matching jnp.round.
// ---------------------------------------------------------------------------
__global__ void quant_kernel(const float4* __restrict__ in, int nvec, int idx) {
    uint2* outv = (idx == 0) ? reinterpret_cast<uint2*>(g_Aq)
                             : reinterpret_cast<uint2*>(g_Bq);
    float amax = __uint_as_float(g_absmax_bits[idx]);
    float s = fmaxf(amax * (1.0f / 448.0f), 1e-12f);
    float inv = 1.0f / s;
    for (int i = blockIdx.x * blockDim.x + threadIdx.x; i < nvec;
         i += gridDim.x * blockDim.x) {
        float4 v = in[i];
        float q0 = rintf(fminf(fmaxf(v.x * inv, -448.0f), 448.0f));
        float q1 = rintf(fminf(fmaxf(v.y * inv, -448.0f), 448.0f));
        float q2 = rintf(fminf(fmaxf(v.z * inv, -448.0f), 448.0f));
        float q3 = rintf(fminf(fmaxf(v.w * inv, -448.0f), 448.0f));
        __half2 h0 = __floats2half2_rn(q0, q1);
        __half2 h1 = __floats2half2_rn(q2, q3);
        uint2 u;
        u.x = *reinterpret_cast<uint32_t*>(&h0);
        u.y = *reinterpret_cast<uint32_t*>(&h1);
        outv[i] = u;
    }
}

// ---------------------------------------------------------------------------
// Pass 3: HMMA GEMM  out[m,n] = (sum_k Aq[m,k]*Bq[n,k]) * scale + bias[n]
// BM=128 x BN=256 x BK=64, 4-stage cp.async pipeline, mma.sync m16n8k16.
// 512 threads = 16 warps in 4(M) x 4(N); warp tile 32 x 64.
// Register fragment double-buffering across the 4 ks-steps.
// ---------------------------------------------------------------------------
__device__ __forceinline__ void load_stage(uint32_t smem_base, int s, int kt,
                                           int m0, int n0, int tid) {
    const uint32_t sa = smem_base + s * STAGE_BYTES;
    const uint32_t sb = sa + A_BYTES;
    const int kbase = kt * BK;
    // A: 128 rows x 8 chunks of 16B = 1024 chunks; 2 per thread
    #pragma unroll
    for (int i = 0; i < 2; i++) {
        int c = tid + i * THREADS;
        int row = c >> 3, col = c & 7;
        const __half* src = g_Aq + (size_t)(m0 + row) * GK + kbase + col * 8;
        cp_async16(sa + swz((uint32_t)(row * 128 + col * 16)), src);
    }
    // B: 256 rows x 8 chunks = 2048 chunks; 4 per thread
    #pragma unroll
    for (int i = 0; i < 4; i++) {
        int c = tid + i * THREADS;
        int row = c >> 3, col = c & 7;
        const __half* src = g_Bq + (size_t)(n0 + row) * GK + kbase + col * 8;
        cp_async16(sb + swz((uint32_t)(row * 128 + col * 16)), src);
    }
}

__global__ void __launch_bounds__(THREADS, 1)
gemm_kernel(const float* __restrict__ bias, float* __restrict__ out) {
    extern __shared__ char smem[];
    const uint32_t smem_base = smem_to_u32(smem);
    const int tid = threadIdx.x;
    const int wid = tid >> 5;
    const int lane = tid & 31;
    const int wm = wid & 3;        // 4 warps along M (32 rows each)
    const int wn = wid >> 2;       // 4 warps along N (64 cols each)

    // Supertile rasterization: bands of 8 m-tiles sweep all n-tiles (L2 reuse)
    int bid = blockIdx.x;
    int band = bid / (RASTER_GROUP * TILES_N);
    int rem  = bid % (RASTER_GROUP * TILES_N);
    int mt = band * RASTER_GROUP + (rem % RASTER_GROUP);
    int nt = rem / RASTER_GROUP;
    const int m0 = mt * BM;
    const int n0 = nt * BN;

    float acc[2][8][4];
    #pragma unroll
    for (int i = 0; i < 2; i++)
        #pragma unroll
        for (int j = 0; j < 8; j++)
            #pragma unroll
            for (int v = 0; v < 4; v++)
                acc[i][j][v] = 0.0f;

    // prologue: fill STAGES-1 stages
    #pragma unroll
    for (int s = 0; s < STAGES - 1; s++) {
        load_stage(smem_base, s, s, m0, n0, tid);
        asm volatile("cp.async.commit_group;\n" ::: "memory");
    }

    // per-lane ldmatrix address components (byte offsets before swizzle)
    const uint32_t lrow = (uint32_t)(lane & 15) * 128u;   // row within 16-row tile
    const uint32_t lcol = (uint32_t)(lane >> 4) * 16u;    // k-half select
    const uint32_t a_off0 = (uint32_t)(wm * 32) * 128u + lrow + lcol;
    const uint32_t b_off0 = (uint32_t)(wn * 64) * 128u + lrow + lcol;

    // fragment double buffers
    uint32_t afr[2][2][4];   // [buf][tm][reg]
    uint32_t bfr[2][4][4];   // [buf][tb][reg]

    #pragma unroll 1
    for (int kt = 0; kt < KITERS; kt++) {
        asm volatile("cp.async.wait_group %0;\n" :: "n"(STAGES - 2) : "memory");
        __syncthreads();

        if (kt + STAGES - 1 < KITERS)
            load_stage(smem_base, (kt + STAGES - 1) % STAGES, kt + STAGES - 1,
                       m0, n0, tid);
        asm volatile("cp.async.commit_group;\n" ::: "memory");

        const uint32_t sa = smem_base + (kt % STAGES) * STAGE_BYTES;
        const uint32_t sb = sa + A_BYTES;

        // preload ks=0 fragments into buf 0
        #pragma unroll
        for (int tm = 0; tm < 2; tm++)
            ldsm_x4(afr[0][tm][0], afr[0][tm][1], afr[0][tm][2], afr[0][tm][3],
                    sa + swz(a_off0 + (uint32_t)(tm * 16) * 128u));
        #pragma unroll
        for (int tb = 0; tb < 4; tb++)
            ldsm_x4(bfr[0][tb][0], bfr[0][tb][1], bfr[0][tb][2], bfr[0][tb][3],
                    sb + swz(b_off0 + (uint32_t)(tb * 16) * 128u));

        #pragma unroll
        for (int ks = 0; ks < 4; ks++) {
            const int cur = ks & 1;
            const int nxt = cur ^ 1;
            if (ks < 3) {   // prefetch next ks fragments while MMAs issue
                const uint32_t koff = (uint32_t)(ks + 1) * 32u;
                #pragma unroll
                for (int tm = 0; tm < 2; tm++)
                    ldsm_x4(afr[nxt][tm][0], afr[nxt][tm][1],
                            afr[nxt][tm][2], afr[nxt][tm][3],
                            sa + swz(a_off0 + koff + (uint32_t)(tm * 16) * 128u));
                #pragma unroll
                for (int tb = 0; tb < 4; tb++)
                    ldsm_x4(bfr[nxt][tb][0], bfr[nxt][tb][1],
                            bfr[nxt][tb][2], bfr[nxt][tb][3],
                            sb + swz(b_off0 + koff + (uint32_t)(tb * 16) * 128u));
            }
            #pragma unroll
            for (int tb = 0; tb < 4; tb++) {
                #pragma unroll
                for (int tm = 0; tm < 2; tm++) {
                    mma16816(acc[tm][tb * 2 + 0],
                             afr[cur][tm][0], afr[cur][tm][1],
                             afr[cur][tm][2], afr[cur][tm][3],
                             bfr[cur][tb][0], bfr[cur][tb][2]);
                    mma16816(acc[tm][tb * 2 + 1],
                             afr[cur][tm][0], afr[cur][tm][1],
                             afr[cur][tm][2], afr[cur][tm][3],
                             bfr[cur][tb][1], bfr[cur][tb][3]);
                }
            }
        }
    }

    // ------------------------------------------------------------------
    // Epilogue: scale + bias
    // ------------------------------------------------------------------
    float s_in = fmaxf(__uint_as_float(g_absmax_bits[0]) * (1.0f / 448.0f), 1e-12f);
    float s_w  = fmaxf(__uint_as_float(g_absmax_bits[1]) * (1.0f / 448.0f), 1e-12f);
    float scale = s_in * s_w;

    const int col0 = n0 + wn * 64 + (lane & 3) * 2;
    float2 bv[8];
    #pragma unroll
    for (int tn = 0; tn < 8; tn++)
        bv[tn] = *reinterpret_cast<const float2*>(bias + col0 + tn * 8);

    #pragma unroll
    for (int tm = 0; tm < 2; tm++) {
        const int row0 = m0 + wm * 32 + tm * 16 + (lane >> 2);
        float* r0 = out + (size_t)row0 * GN;
        float* r1 = r0 + 8 * GN;
        #pragma unroll
        for (int tn = 0; tn < 8; tn++) {
            const int c = col0 + tn * 8;
            float2 v0, v1;
            v0.x = acc[tm][tn][0] * scale + bv[tn].x;
            v0.y = acc[tm][tn][1] * scale + bv[tn].y;
            v1.x = acc[tm][tn][2] * scale + bv[tn].x;
            v1.y = acc[tm][tn][3] * scale + bv[tn].y;
            *reinterpret_cast<float2*>(r0 + c) = v0;
            *reinterpret_cast<float2*>(r1 + c) = v1;
        }
    }
}

// ---------------------------------------------------------------------------
// Launch
// ---------------------------------------------------------------------------
extern "C" void kernel_launch(void* const* d_in, const int* in_sizes, int n_in,
                              void* d_out, int out_size) {
    const float* x    = (const float*)d_in[0];
    const float* w    = (const float*)d_in[1];
    const float* bias = (const float*)d_in[2];
    float* out        = (float*)d_out;

    init_kernel<<<1, 1>>>();
    absmax_kernel<<<2048, 256>>>((const float4*)x, (GM * GK) / 4, 0);
    absmax_kernel<<<1024, 256>>>((const float4*)w, (GN * GK) / 4, 1);
    quant_kernel<<<2048, 256>>>((const float4*)x, (GM * GK) / 4, 0);
    quant_kernel<<<1024, 256>>>((const float4*)w, (GN * GK) / 4, 1);

    cudaFuncSetAttribute(gemm_kernel,
                         cudaFuncAttributeMaxDynamicSharedMemorySize, SMEM_TOTAL);
    gemm_kernel<<<NBLOCKS, THREADS, SMEM_TOTAL>>>(bias, out);
}